// round 1
// baseline (speedup 1.0000x reference)
#include <cuda_runtime.h>
#include <math.h>

#define B_ 64
#define L_ 2048
#define C_ 512
#define R_ 64

// Scratch (static device globals — no allocation APIs)
__device__ float g_hlow[B_ * C_ * R_];   // (B, C, R) 8 MB
__device__ float g_hattn[B_ * C_ * R_];  // (B, C, R) 8 MB

// ---------------------------------------------------------------------------
// Kernel 1: h_low[b,c,r] = sum_l x[b,l,c] * Wd[r,l] + bd[r]
// Grid (C/64, B), 256 threads. 64c x 64r tile per CTA, K-tiles of 32.
// ---------------------------------------------------------------------------
__global__ __launch_bounds__(256) void k_hlow(const float* __restrict__ x,
                                              const float* __restrict__ Wd,
                                              const float* __restrict__ bd) {
    __shared__ float xs[32][64];    // xs[k][c]
    __shared__ float wds[32][65];   // wds[k][r] (pad 65: conflict-free stores)

    const int b = blockIdx.y;
    const int c0 = blockIdx.x * 64;
    const int tid = threadIdx.x;
    const int tx = tid & 15;   // c-sub (x4)
    const int ty = tid >> 4;   // r-sub (x4)

    const float* xb = x + (size_t)b * L_ * C_;

    float acc[4][4];
#pragma unroll
    for (int i = 0; i < 4; i++)
#pragma unroll
        for (int j = 0; j < 4; j++) acc[i][j] = 0.f;

    for (int l0 = 0; l0 < L_; l0 += 32) {
        // load x tile: 32 rows x 64 c (512 float4)
#pragma unroll
        for (int i = 0; i < 2; i++) {
            int idx4 = tid + i * 256;
            int k = idx4 >> 4, c4 = (idx4 & 15) * 4;
            float4 v = *(const float4*)&xb[(size_t)(l0 + k) * C_ + c0 + c4];
            *(float4*)&xs[k][c4] = v;
        }
        // load Wd tile transposed: wds[k][r] = Wd[r][l0+k]
#pragma unroll
        for (int i = 0; i < 8; i++) {
            int idx = tid + i * 256;
            int r = idx >> 5, k = idx & 31;
            wds[k][r] = Wd[r * L_ + l0 + k];
        }
        __syncthreads();

#pragma unroll
        for (int kk = 0; kk < 32; kk++) {
            float4 a = *(float4*)&xs[kk][tx * 4];
            float av[4] = {a.x, a.y, a.z, a.w};
#pragma unroll
            for (int i = 0; i < 4; i++) {
                float wv = wds[kk][ty * 4 + i];
#pragma unroll
                for (int j = 0; j < 4; j++) acc[i][j] += wv * av[j];
            }
        }
        __syncthreads();
    }

    float bdv[4];
#pragma unroll
    for (int i = 0; i < 4; i++) bdv[i] = bd[ty * 4 + i];

#pragma unroll
    for (int j = 0; j < 4; j++) {
        int c = c0 + tx * 4 + j;
        float4 o;
        o.x = acc[0][j] + bdv[0];
        o.y = acc[1][j] + bdv[1];
        o.z = acc[2][j] + bdv[2];
        o.w = acc[3][j] + bdv[3];
        *(float4*)&g_hlow[((b * C_) + c) * R_ + ty * 4] = o;
    }
}

// ---------------------------------------------------------------------------
// Kernel 2: per batch — Q,K,V,gate, global KV reduction, h_attn.
// Grid (B), 256 threads (8 warps; each warp owns a token per iteration,
// each lane owns output channels {lane, lane+32}).
// ---------------------------------------------------------------------------
__global__ __launch_bounds__(256) void k_attn(const float* __restrict__ Wq,
                                              const float* __restrict__ Wk,
                                              const float* __restrict__ Wv,
                                              const float* __restrict__ Wg,
                                              const float* __restrict__ bg) {
    __shared__ float wA[64 * 65];  // transposed weight: wA[s*65 + o] = W[o][s]
    __shared__ float wB[64 * 65];
    __shared__ float kv[64];

    const int b = blockIdx.x;
    const int tid = threadIdx.x;
    const int lane = tid & 31;
    const int w = tid >> 5;

    if (tid < 64) kv[tid] = 0.f;
    // Phase A weights: Wk -> wA, Wv -> wB (transposed, padded)
#pragma unroll
    for (int i = 0; i < 16; i++) {
        int idx = tid + i * 256;
        int o = idx >> 6, s = idx & 63;
        wA[s * 65 + o] = Wk[idx];
        wB[s * 65 + o] = Wv[idx];
    }
    __syncthreads();

    float acc0 = 0.f, acc1 = 0.f;
    for (int it = 0; it < 64; it++) {
        int c = it * 8 + w;
        const float* hb = &g_hlow[((b * C_) + c) * R_];
        float h0 = hb[lane], h1 = hb[lane + 32];
        float k0 = 0.f, k1 = 0.f, v0 = 0.f, v1 = 0.f;
#pragma unroll
        for (int s = 0; s < 32; s++) {
            float ha = __shfl_sync(0xffffffffu, h0, s);
            float hc = __shfl_sync(0xffffffffu, h1, s);
            k0 += ha * wA[s * 65 + lane] + hc * wA[(s + 32) * 65 + lane];
            k1 += ha * wA[s * 65 + lane + 32] + hc * wA[(s + 32) * 65 + lane + 32];
            v0 += ha * wB[s * 65 + lane] + hc * wB[(s + 32) * 65 + lane];
            v1 += ha * wB[s * 65 + lane + 32] + hc * wB[(s + 32) * 65 + lane + 32];
        }
        float nk = k0 * k0 + k1 * k1;
#pragma unroll
        for (int off = 16; off > 0; off >>= 1) nk += __shfl_xor_sync(0xffffffffu, nk, off);
        float inv = 1.f / fmaxf(sqrtf(nk), 1e-12f);
        acc0 += k0 * inv * v0;
        acc1 += k1 * inv * v1;
    }
    atomicAdd(&kv[lane], acc0);
    atomicAdd(&kv[lane + 32], acc1);
    __syncthreads();

    // Phase B weights: Wq -> wA, Wg -> wB
#pragma unroll
    for (int i = 0; i < 16; i++) {
        int idx = tid + i * 256;
        int o = idx >> 6, s = idx & 63;
        wA[s * 65 + o] = Wq[idx];
        wB[s * 65 + o] = Wg[idx];
    }
    float kv0t = kv[lane], kv1t = kv[lane + 32];  // kv complete after first sync
    float bg0 = bg[lane], bg1 = bg[lane + 32];
    __syncthreads();

    for (int it = 0; it < 64; it++) {
        int c = it * 8 + w;
        const float* hb = &g_hlow[((b * C_) + c) * R_];
        float h0 = hb[lane], h1 = hb[lane + 32];
        float q0 = 0.f, q1 = 0.f, g0 = 0.f, g1 = 0.f;
#pragma unroll
        for (int s = 0; s < 32; s++) {
            float ha = __shfl_sync(0xffffffffu, h0, s);
            float hc = __shfl_sync(0xffffffffu, h1, s);
            q0 += ha * wA[s * 65 + lane] + hc * wA[(s + 32) * 65 + lane];
            q1 += ha * wA[s * 65 + lane + 32] + hc * wA[(s + 32) * 65 + lane + 32];
            g0 += ha * wB[s * 65 + lane] + hc * wB[(s + 32) * 65 + lane];
            g1 += ha * wB[s * 65 + lane + 32] + hc * wB[(s + 32) * 65 + lane + 32];
        }
        float nq = q0 * q0 + q1 * q1;
#pragma unroll
        for (int off = 16; off > 0; off >>= 1) nq += __shfl_xor_sync(0xffffffffu, nq, off);
        float inv = 1.f / fmaxf(sqrtf(nq), 1e-12f);
        float ga0 = 1.f / (1.f + expf(-(g0 + bg0)));
        float ga1 = 1.f / (1.f + expf(-(g1 + bg1)));
        float* ob = &g_hattn[((b * C_) + c) * R_];
        ob[lane]      = q0 * inv * kv0t * ga0;
        ob[lane + 32] = q1 * inv * kv1t * ga1;
    }
}

// ---------------------------------------------------------------------------
// Kernel 3: out[b,l,c] = LN_c( x[b,l,c] + alpha*(h_attn[b,c,:]·Wu[l,:] + bu[l]) )
// Grid (L/32, B), 256 threads. Per CTA: 32 l rows x all 512 c, c-tiled by 128.
// Full (32 x 512) pre-LN tile kept in smem -> single-pass LN, single write.
// ---------------------------------------------------------------------------
__global__ __launch_bounds__(256) void k_out(const float* __restrict__ x,
                                             const float* __restrict__ Wu,
                                             const float* __restrict__ bu,
                                             const float* __restrict__ gamma,
                                             const float* __restrict__ beta,
                                             const float* __restrict__ alpha_p,
                                             float* __restrict__ out) {
    extern __shared__ float sm[];
    float* ha = sm;                   // [64][132]  (r-major, padded)
    float* wu = sm + 64 * 132;        // [32][64]
    float* outs = wu + 32 * 64;       // [32][512]

    const int b = blockIdx.y;
    const int l0 = blockIdx.x * 32;
    const int tid = threadIdx.x;
    const int tx = tid & 31;   // c-sub (x4) over 128
    const int ty = tid >> 5;   // l-sub (x4) over 32
    const float alpha = *alpha_p;

#pragma unroll
    for (int i = 0; i < 8; i++) {
        int idx = tid + i * 256;
        wu[idx] = Wu[(size_t)l0 * R_ + idx];
    }
    float bul[4];
#pragma unroll
    for (int i = 0; i < 4; i++) bul[i] = bu[l0 + ty * 4 + i];

    for (int ct = 0; ct < 4; ct++) {
        const int c0 = ct * 128;
        __syncthreads();  // protect ha reuse (and wu/bul on first iter)
#pragma unroll 8
        for (int i = 0; i < 32; i++) {
            int idx = tid + i * 256;
            int ci = idx >> 6, r = idx & 63;
            ha[r * 132 + ci] = g_hattn[((b * C_) + c0 + ci) * R_ + r];
        }
        __syncthreads();

        float acc[4][4];
#pragma unroll
        for (int i = 0; i < 4; i++)
#pragma unroll
            for (int j = 0; j < 4; j++) acc[i][j] = 0.f;

#pragma unroll 8
        for (int kk = 0; kk < 64; kk++) {
            float4 a = *(float4*)&ha[kk * 132 + tx * 4];
            float av[4] = {a.x, a.y, a.z, a.w};
#pragma unroll
            for (int i = 0; i < 4; i++) {
                float wv = wu[(ty * 4 + i) * 64 + kk];
#pragma unroll
                for (int j = 0; j < 4; j++) acc[i][j] += wv * av[j];
            }
        }

#pragma unroll
        for (int i = 0; i < 4; i++) {
            int li = ty * 4 + i;
            size_t xoff = ((size_t)b * L_ + l0 + li) * C_ + c0 + tx * 4;
            float4 xv = *(const float4*)&x[xoff];
            float4 o;
            o.x = xv.x + alpha * (acc[i][0] + bul[i]);
            o.y = xv.y + alpha * (acc[i][1] + bul[i]);
            o.z = xv.z + alpha * (acc[i][2] + bul[i]);
            o.w = xv.w + alpha * (acc[i][3] + bul[i]);
            *(float4*)&outs[li * 512 + c0 + tx * 4] = o;
        }
    }
    __syncthreads();

    // LayerNorm over c for each of the 32 l rows (warp ty handles 4 rows)
#pragma unroll
    for (int rr = 0; rr < 4; rr++) {
        int li = ty * 4 + rr;
        float s = 0.f, ss = 0.f;
#pragma unroll
        for (int k = 0; k < 16; k++) {
            float v = outs[li * 512 + tx + 32 * k];
            s += v;
            ss += v * v;
        }
#pragma unroll
        for (int off = 16; off > 0; off >>= 1) {
            s += __shfl_xor_sync(0xffffffffu, s, off);
            ss += __shfl_xor_sync(0xffffffffu, ss, off);
        }
        float mu = s * (1.f / 512.f);
        float var = ss * (1.f / 512.f) - mu * mu;
        float rstd = rsqrtf(var + 1e-5f);
        size_t obase = ((size_t)b * L_ + l0 + li) * C_;
#pragma unroll
        for (int k = 0; k < 16; k++) {
            int c = tx + 32 * k;
            float v = outs[li * 512 + c];
            out[obase + c] = (v - mu) * rstd * gamma[c] + beta[c];
        }
    }
}

// ---------------------------------------------------------------------------
extern "C" void kernel_launch(void* const* d_in, const int* in_sizes, int n_in,
                              void* d_out, int out_size) {
    const float* x     = (const float*)d_in[0];
    const float* Wd    = (const float*)d_in[1];
    const float* bd    = (const float*)d_in[2];
    const float* Wq    = (const float*)d_in[3];
    const float* Wk    = (const float*)d_in[4];
    const float* Wv    = (const float*)d_in[5];
    const float* Wg    = (const float*)d_in[6];
    const float* bg    = (const float*)d_in[7];
    const float* Wu    = (const float*)d_in[8];
    const float* bu    = (const float*)d_in[9];
    const float* gamma = (const float*)d_in[10];
    const float* beta  = (const float*)d_in[11];
    const float* alpha = (const float*)d_in[12];
    float* out = (float*)d_out;

    static const int smem3 = (64 * 132 + 32 * 64 + 32 * 512) * 4;  // 107520 B
    cudaFuncSetAttribute(k_out, cudaFuncAttributeMaxDynamicSharedMemorySize, smem3);

    k_hlow<<<dim3(C_ / 64, B_), 256>>>(x, Wd, bd);
    k_attn<<<B_, 256>>>(Wq, Wk, Wv, Wg, bg);
    k_out<<<dim3(L_ / 32, B_), 256, smem3>>>(x, Wu, bu, gamma, beta, alpha, out);
}

// round 2
// speedup vs baseline: 3.8292x; 3.8292x over previous
#include <cuda_runtime.h>
#include <math.h>
#include <stdint.h>

#define B_ 64
#define L_ 2048
#define C_ 512
#define R_ 64

// Scratch (static device globals — no allocation APIs)
__device__ float g_hlow[B_ * C_ * R_];    // (B, C, R)
__device__ float g_hattn[B_ * C_ * R_];   // (B, C, R)
__device__ float g_kvpart[B_ * 8 * 64];   // per-(b, chunk) partial kv sums

__device__ __forceinline__ uint32_t tf32_of(float x) {
    uint32_t r;
    asm("cvt.rna.tf32.f32 %0, %1;" : "=r"(r) : "f"(x));
    return r;
}

__device__ __forceinline__ void mma_tf32(float c[4],
                                         uint32_t a0, uint32_t a1, uint32_t a2, uint32_t a3,
                                         uint32_t b0, uint32_t b1) {
    asm volatile(
        "mma.sync.aligned.m16n8k8.row.col.f32.tf32.tf32.f32 "
        "{%0,%1,%2,%3}, {%4,%5,%6,%7}, {%8,%9}, {%0,%1,%2,%3};\n"
        : "+f"(c[0]), "+f"(c[1]), "+f"(c[2]), "+f"(c[3])
        : "r"(a0), "r"(a1), "r"(a2), "r"(a3), "r"(b0), "r"(b1));
}

// ---------------------------------------------------------------------------
// Kernel 1 (tf32 mma): h_low[b,c,r] = sum_l x[b,l,c]*Wd[r,l] + bd[r]
// Grid (4, B), 256 thr. CTA tile 128c x 64r, K-chunks of 32, reg prefetch.
// Warps: 4 along c (32 each) x 2 along r (32 each). m=c, n=r, k=l.
// ---------------------------------------------------------------------------
__global__ __launch_bounds__(256) void k_hlow(const float* __restrict__ x,
                                              const float* __restrict__ Wd,
                                              const float* __restrict__ bd) {
    __shared__ uint32_t as[32][136];  // [k][c], stride 136 -> bank = 8k + c
    __shared__ uint32_t bs[64][40];   // [r][k], stride 40  -> bank = 8r + k

    const int b = blockIdx.y;
    const int cBase = blockIdx.x * 128;
    const int tid = threadIdx.x;
    const int wid = tid >> 5;
    const int lane = tid & 31;
    const int group = lane >> 2;
    const int t4 = lane & 3;
    const int warpC = (wid & 3) * 32;
    const int warpR = (wid >> 2) * 32;

    const float* xb = x + (size_t)b * L_ * C_ + cBase;

    float acc[2][4][4];
#pragma unroll
    for (int mt = 0; mt < 2; mt++)
#pragma unroll
        for (int nt = 0; nt < 4; nt++)
#pragma unroll
            for (int i = 0; i < 4; i++) acc[mt][nt][i] = 0.f;

    float4 xr[4];
    float wr[8];

    // --- prefetch chunk 0 into regs ---
#pragma unroll
    for (int i = 0; i < 4; i++) {
        int idx4 = tid + i * 256;
        int k = idx4 >> 5, c4 = (idx4 & 31) * 4;
        xr[i] = *(const float4*)&xb[(size_t)k * C_ + c4];
    }
#pragma unroll
    for (int i = 0; i < 8; i++) {
        int idx = tid + i * 256;
        int r = idx >> 5, k = idx & 31;
        wr[i] = Wd[r * L_ + k];
    }
    // regs -> smem
#pragma unroll
    for (int i = 0; i < 4; i++) {
        int idx4 = tid + i * 256;
        int k = idx4 >> 5, c4 = (idx4 & 31) * 4;
        as[k][c4 + 0] = tf32_of(xr[i].x);
        as[k][c4 + 1] = tf32_of(xr[i].y);
        as[k][c4 + 2] = tf32_of(xr[i].z);
        as[k][c4 + 3] = tf32_of(xr[i].w);
    }
#pragma unroll
    for (int i = 0; i < 8; i++) {
        int idx = tid + i * 256;
        int r = idx >> 5, k = idx & 31;
        bs[r][k] = tf32_of(wr[i]);
    }
    __syncthreads();

    for (int ch = 0; ch < 64; ch++) {
        // prefetch next chunk (gmem -> regs) while mma runs on current smem
        if (ch < 63) {
            int l0 = (ch + 1) * 32;
#pragma unroll
            for (int i = 0; i < 4; i++) {
                int idx4 = tid + i * 256;
                int k = idx4 >> 5, c4 = (idx4 & 31) * 4;
                xr[i] = *(const float4*)&xb[(size_t)(l0 + k) * C_ + c4];
            }
#pragma unroll
            for (int i = 0; i < 8; i++) {
                int idx = tid + i * 256;
                int r = idx >> 5, k = idx & 31;
                wr[i] = Wd[r * L_ + l0 + k];
            }
        }

#pragma unroll
        for (int ks = 0; ks < 4; ks++) {
            int k0 = ks * 8 + t4;
            uint32_t a[2][4];
#pragma unroll
            for (int mt = 0; mt < 2; mt++) {
                int cm = warpC + mt * 16 + group;
                a[mt][0] = as[k0][cm];
                a[mt][1] = as[k0][cm + 8];
                a[mt][2] = as[k0 + 4][cm];
                a[mt][3] = as[k0 + 4][cm + 8];
            }
#pragma unroll
            for (int nt = 0; nt < 4; nt++) {
                int rn = warpR + nt * 8 + group;
                uint32_t b0 = bs[rn][k0];
                uint32_t b1 = bs[rn][k0 + 4];
#pragma unroll
                for (int mt = 0; mt < 2; mt++)
                    mma_tf32(acc[mt][nt], a[mt][0], a[mt][1], a[mt][2], a[mt][3], b0, b1);
            }
        }
        __syncthreads();
        if (ch < 63) {
#pragma unroll
            for (int i = 0; i < 4; i++) {
                int idx4 = tid + i * 256;
                int k = idx4 >> 5, c4 = (idx4 & 31) * 4;
                as[k][c4 + 0] = tf32_of(xr[i].x);
                as[k][c4 + 1] = tf32_of(xr[i].y);
                as[k][c4 + 2] = tf32_of(xr[i].z);
                as[k][c4 + 3] = tf32_of(xr[i].w);
            }
#pragma unroll
            for (int i = 0; i < 8; i++) {
                int idx = tid + i * 256;
                int r = idx >> 5, k = idx & 31;
                bs[r][k] = tf32_of(wr[i]);
            }
            __syncthreads();
        }
    }

    // epilogue: acc -> g_hlow, add bd
#pragma unroll
    for (int nt = 0; nt < 4; nt++) {
        int r = warpR + nt * 8 + t4 * 2;
        float b0v = bd[r], b1v = bd[r + 1];
#pragma unroll
        for (int mt = 0; mt < 2; mt++) {
            int c = cBase + warpC + mt * 16 + group;
            float2 v0 = {acc[mt][nt][0] + b0v, acc[mt][nt][1] + b1v};
            float2 v1 = {acc[mt][nt][2] + b0v, acc[mt][nt][3] + b1v};
            *(float2*)&g_hlow[((size_t)b * C_ + c) * R_ + r] = v0;
            *(float2*)&g_hlow[((size_t)b * C_ + c + 8) * R_ + r] = v1;
        }
    }
}

// ---------------------------------------------------------------------------
// Kernel 2a: partial kv sums. Grid (8, B), 256 thr; chunk = 64 tokens.
// ---------------------------------------------------------------------------
__global__ __launch_bounds__(256) void k_kv(const float* __restrict__ Wk,
                                            const float* __restrict__ Wv) {
    __shared__ float wA[64 * 65];
    __shared__ float wB[64 * 65];
    __shared__ float kv[64];

    const int b = blockIdx.y;
    const int chunk = blockIdx.x;
    const int tid = threadIdx.x;
    const int lane = tid & 31;
    const int w = tid >> 5;

    if (tid < 64) kv[tid] = 0.f;
#pragma unroll
    for (int i = 0; i < 16; i++) {
        int idx = tid + i * 256;
        int o = idx >> 6, s = idx & 63;
        wA[s * 65 + o] = Wk[idx];
        wB[s * 65 + o] = Wv[idx];
    }
    __syncthreads();

    float acc0 = 0.f, acc1 = 0.f;
#pragma unroll
    for (int it = 0; it < 8; it++) {
        int c = chunk * 64 + it * 8 + w;
        const float* hb = &g_hlow[((size_t)b * C_ + c) * R_];
        float h0 = hb[lane], h1 = hb[lane + 32];
        float k0 = 0.f, k1 = 0.f, v0 = 0.f, v1 = 0.f;
#pragma unroll
        for (int s = 0; s < 32; s++) {
            float ha = __shfl_sync(0xffffffffu, h0, s);
            float hc = __shfl_sync(0xffffffffu, h1, s);
            k0 += ha * wA[s * 65 + lane] + hc * wA[(s + 32) * 65 + lane];
            k1 += ha * wA[s * 65 + lane + 32] + hc * wA[(s + 32) * 65 + lane + 32];
            v0 += ha * wB[s * 65 + lane] + hc * wB[(s + 32) * 65 + lane];
            v1 += ha * wB[s * 65 + lane + 32] + hc * wB[(s + 32) * 65 + lane + 32];
        }
        float nk = k0 * k0 + k1 * k1;
#pragma unroll
        for (int off = 16; off > 0; off >>= 1) nk += __shfl_xor_sync(0xffffffffu, nk, off);
        float inv = 1.f / fmaxf(sqrtf(nk), 1e-12f);
        acc0 += k0 * inv * v0;
        acc1 += k1 * inv * v1;
    }
    atomicAdd(&kv[lane], acc0);
    atomicAdd(&kv[lane + 32], acc1);
    __syncthreads();
    if (tid < 64) g_kvpart[((size_t)b * 8 + chunk) * 64 + tid] = kv[tid];
}

// ---------------------------------------------------------------------------
// Kernel 2b: Q, gate, h_attn using summed kv. Grid (8, B), 256 thr.
// ---------------------------------------------------------------------------
__global__ __launch_bounds__(256) void k_qg(const float* __restrict__ Wq,
                                            const float* __restrict__ Wg,
                                            const float* __restrict__ bg) {
    __shared__ float wA[64 * 65];
    __shared__ float wB[64 * 65];
    __shared__ float kv[64];

    const int b = blockIdx.y;
    const int chunk = blockIdx.x;
    const int tid = threadIdx.x;
    const int lane = tid & 31;
    const int w = tid >> 5;

    if (tid < 64) {
        float s = 0.f;
#pragma unroll
        for (int j = 0; j < 8; j++) s += g_kvpart[((size_t)b * 8 + j) * 64 + tid];
        kv[tid] = s;
    }
#pragma unroll
    for (int i = 0; i < 16; i++) {
        int idx = tid + i * 256;
        int o = idx >> 6, s = idx & 63;
        wA[s * 65 + o] = Wq[idx];
        wB[s * 65 + o] = Wg[idx];
    }
    __syncthreads();

    float kv0t = kv[lane], kv1t = kv[lane + 32];
    float bg0 = bg[lane], bg1 = bg[lane + 32];

#pragma unroll
    for (int it = 0; it < 8; it++) {
        int c = chunk * 64 + it * 8 + w;
        const float* hb = &g_hlow[((size_t)b * C_ + c) * R_];
        float h0 = hb[lane], h1 = hb[lane + 32];
        float q0 = 0.f, q1 = 0.f, g0 = 0.f, g1 = 0.f;
#pragma unroll
        for (int s = 0; s < 32; s++) {
            float ha = __shfl_sync(0xffffffffu, h0, s);
            float hc = __shfl_sync(0xffffffffu, h1, s);
            q0 += ha * wA[s * 65 + lane] + hc * wA[(s + 32) * 65 + lane];
            q1 += ha * wA[s * 65 + lane + 32] + hc * wA[(s + 32) * 65 + lane + 32];
            g0 += ha * wB[s * 65 + lane] + hc * wB[(s + 32) * 65 + lane];
            g1 += ha * wB[s * 65 + lane + 32] + hc * wB[(s + 32) * 65 + lane + 32];
        }
        float nq = q0 * q0 + q1 * q1;
#pragma unroll
        for (int off = 16; off > 0; off >>= 1) nq += __shfl_xor_sync(0xffffffffu, nq, off);
        float inv = 1.f / fmaxf(sqrtf(nq), 1e-12f);
        float ga0 = 1.f / (1.f + expf(-(g0 + bg0)));
        float ga1 = 1.f / (1.f + expf(-(g1 + bg1)));
        float* ob = &g_hattn[((size_t)b * C_ + c) * R_];
        ob[lane]      = q0 * inv * kv0t * ga0;
        ob[lane + 32] = q1 * inv * kv1t * ga1;
    }
}

// ---------------------------------------------------------------------------
// Kernel 3 (tf32 mma): mixed[l,c] = sum_r Wu[l,r]*h_attn[c,r];
// out = LN_c(x + alpha*(mixed + bu)). Grid (64, B), 256 thr.
// CTA tile: 32 l (m) x 512 c (n), k = 64 in 2 chunks of 32.
// Warps: each warp owns n=64 c (8 ntiles) x m=32 (2 mtiles).
// ---------------------------------------------------------------------------
__global__ __launch_bounds__(256) void k_out(const float* __restrict__ x,
                                             const float* __restrict__ Wu,
                                             const float* __restrict__ bu,
                                             const float* __restrict__ gamma,
                                             const float* __restrict__ beta,
                                             const float* __restrict__ alpha_p,
                                             float* __restrict__ out) {
    extern __shared__ float sm[];
    uint32_t* as = (uint32_t*)sm;              // [32][72]  Wu tile (full k)
    uint32_t* bs = (uint32_t*)(sm + 32 * 72);  // [512][36] h_attn k-chunk
    float* outs = sm;                          // alias after mma: [32][516]

    const int b = blockIdx.y;
    const int l0 = blockIdx.x * 32;
    const int tid = threadIdx.x;
    const int wid = tid >> 5;
    const int lane = tid & 31;
    const int group = lane >> 2;
    const int t4 = lane & 3;

    float acc[2][8][4];
#pragma unroll
    for (int mt = 0; mt < 2; mt++)
#pragma unroll
        for (int nt = 0; nt < 8; nt++)
#pragma unroll
            for (int i = 0; i < 4; i++) acc[mt][nt][i] = 0.f;

    // load A = Wu tile [32 l][64 k]
#pragma unroll
    for (int i = 0; i < 8; i++) {
        int idx = tid + i * 256;
        int l = idx >> 6, k = idx & 63;
        as[l * 72 + k] = tf32_of(Wu[(size_t)(l0 + l) * R_ + k]);
    }

    for (int kc = 0; kc < 64; kc += 32) {
        __syncthreads();
        // load B chunk: bs[c][kk] = h_attn[b][c][kc+kk], 512c x 32k
#pragma unroll
        for (int i = 0; i < 16; i++) {
            int idx4 = tid + i * 256;
            int c = idx4 >> 3, kq = (idx4 & 7) * 4;
            float4 v = *(const float4*)&g_hattn[((size_t)b * C_ + c) * R_ + kc + kq];
            bs[c * 36 + kq + 0] = tf32_of(v.x);
            bs[c * 36 + kq + 1] = tf32_of(v.y);
            bs[c * 36 + kq + 2] = tf32_of(v.z);
            bs[c * 36 + kq + 3] = tf32_of(v.w);
        }
        __syncthreads();

#pragma unroll
        for (int ks = 0; ks < 4; ks++) {
            int k0 = ks * 8 + t4;
            uint32_t a[2][4];
#pragma unroll
            for (int mt = 0; mt < 2; mt++) {
                int lm = mt * 16 + group;
                a[mt][0] = as[lm * 72 + kc + k0];
                a[mt][1] = as[(lm + 8) * 72 + kc + k0];
                a[mt][2] = as[lm * 72 + kc + k0 + 4];
                a[mt][3] = as[(lm + 8) * 72 + kc + k0 + 4];
            }
#pragma unroll
            for (int nt = 0; nt < 8; nt++) {
                int cn = wid * 64 + nt * 8 + group;
                uint32_t b0 = bs[cn * 36 + k0];
                uint32_t b1 = bs[cn * 36 + k0 + 4];
#pragma unroll
                for (int mt = 0; mt < 2; mt++)
                    mma_tf32(acc[mt][nt], a[mt][0], a[mt][1], a[mt][2], a[mt][3], b0, b1);
            }
        }
    }
    __syncthreads();  // all smem mma reads done; alias outs over as/bs

    // epilogue: mixed -> outs
#pragma unroll
    for (int mt = 0; mt < 2; mt++) {
        int l = mt * 16 + group;
#pragma unroll
        for (int nt = 0; nt < 8; nt++) {
            int c = wid * 64 + nt * 8 + t4 * 2;
            float2 v0 = {acc[mt][nt][0], acc[mt][nt][1]};
            float2 v1 = {acc[mt][nt][2], acc[mt][nt][3]};
            *(float2*)&outs[l * 516 + c] = v0;
            *(float2*)&outs[(l + 8) * 516 + c] = v1;
        }
    }
    __syncthreads();

    // residual + LN over c, warp wid handles 4 rows
    const float alpha = *alpha_p;
#pragma unroll
    for (int rr = 0; rr < 4; rr++) {
        int li = wid * 4 + rr;
        float bul = bu[l0 + li];
        size_t xbase = ((size_t)b * L_ + l0 + li) * C_;
        float s = 0.f, ss = 0.f;
#pragma unroll
        for (int k = 0; k < 16; k++) {
            int c = lane + 32 * k;
            float m = outs[li * 516 + c];
            float v = x[xbase + c] + alpha * (m + bul);
            outs[li * 516 + c] = v;
            s += v;
            ss += v * v;
        }
#pragma unroll
        for (int off = 16; off > 0; off >>= 1) {
            s += __shfl_xor_sync(0xffffffffu, s, off);
            ss += __shfl_xor_sync(0xffffffffu, ss, off);
        }
        float mu = s * (1.f / 512.f);
        float var = ss * (1.f / 512.f) - mu * mu;
        float rstd = rsqrtf(var + 1e-5f);
#pragma unroll
        for (int k = 0; k < 16; k++) {
            int c = lane + 32 * k;
            float v = outs[li * 516 + c];
            out[xbase + c] = (v - mu) * rstd * gamma[c] + beta[c];
        }
    }
}

// ---------------------------------------------------------------------------
extern "C" void kernel_launch(void* const* d_in, const int* in_sizes, int n_in,
                              void* d_out, int out_size) {
    const float* x     = (const float*)d_in[0];
    const float* Wd    = (const float*)d_in[1];
    const float* bd    = (const float*)d_in[2];
    const float* Wq    = (const float*)d_in[3];
    const float* Wk    = (const float*)d_in[4];
    const float* Wv    = (const float*)d_in[5];
    const float* Wg    = (const float*)d_in[6];
    const float* bg    = (const float*)d_in[7];
    const float* Wu    = (const float*)d_in[8];
    const float* bu    = (const float*)d_in[9];
    const float* gamma = (const float*)d_in[10];
    const float* beta  = (const float*)d_in[11];
    const float* alpha = (const float*)d_in[12];
    float* out = (float*)d_out;

    static const int smem3 = (32 * 72 + 512 * 36) * 4;  // 82944 B
    static bool attr_set = false;
    if (!attr_set) {
        cudaFuncSetAttribute(k_out, cudaFuncAttributeMaxDynamicSharedMemorySize, smem3);
        attr_set = true;
    }

    k_hlow<<<dim3(4, B_), 256>>>(x, Wd, bd);
    k_kv<<<dim3(8, B_), 256>>>(Wk, Wv);
    k_qg<<<dim3(8, B_), 256>>>(Wq, Wg, bg);
    k_out<<<dim3(64, B_), 256, smem3>>>(x, Wu, bu, gamma, beta, alpha, out);
}

// round 3
// speedup vs baseline: 4.3482x; 1.1355x over previous
#include <cuda_runtime.h>
#include <cuda_bf16.h>
#include <math.h>
#include <stdint.h>

#define B_ 64
#define L_ 2048
#define C_ 512
#define R_ 64

// Scratch (static device globals — no allocation APIs)
__device__ float g_hlow[B_ * C_ * R_];                          // (B, C, R) fp32
__device__ __align__(16) __nv_bfloat16 g_hattn[B_ * C_ * R_];   // (B, C, R) bf16
__device__ float g_kvpart[B_ * 8 * 64];

__device__ __forceinline__ void mma_tf32(float c[4],
                                         uint32_t a0, uint32_t a1, uint32_t a2, uint32_t a3,
                                         uint32_t b0, uint32_t b1) {
    asm volatile(
        "mma.sync.aligned.m16n8k8.row.col.f32.tf32.tf32.f32 "
        "{%0,%1,%2,%3}, {%4,%5,%6,%7}, {%8,%9}, {%0,%1,%2,%3};\n"
        : "+f"(c[0]), "+f"(c[1]), "+f"(c[2]), "+f"(c[3])
        : "r"(a0), "r"(a1), "r"(a2), "r"(a3), "r"(b0), "r"(b1));
}

__device__ __forceinline__ void mma_bf16(float c[4],
                                         uint32_t a0, uint32_t a1, uint32_t a2, uint32_t a3,
                                         uint32_t b0, uint32_t b1) {
    asm volatile(
        "mma.sync.aligned.m16n8k16.row.col.f32.bf16.bf16.f32 "
        "{%0,%1,%2,%3}, {%4,%5,%6,%7}, {%8,%9}, {%0,%1,%2,%3};\n"
        : "+f"(c[0]), "+f"(c[1]), "+f"(c[2]), "+f"(c[3])
        : "r"(a0), "r"(a1), "r"(a2), "r"(a3), "r"(b0), "r"(b1));
}

// ---------------------------------------------------------------------------
// Kernel 1 (tf32 mma + cp.async double buffer):
// h_low[b,c,r] = sum_l x[b,l,c]*Wd[r,l] + bd[r]
// Grid (8, B), 256 thr. Tile 64c x 64r, K-chunks of 64. No explicit tf32 cvt
// (HMMA truncates fp32 operands to tf32).
// Warps: 2 along c (32) x 4 along r (16). m=c, n=r, k=l.
// ---------------------------------------------------------------------------
__global__ __launch_bounds__(256, 3) void k_hlow(const float* __restrict__ x,
                                                 const float* __restrict__ Wd,
                                                 const float* __restrict__ bd) {
    extern __shared__ float smh[];
    // layout: as[2][64][72], bs[2][64][72]  (floats)
    const int b = blockIdx.y;
    const int c0 = blockIdx.x * 64;
    const int tid = threadIdx.x;
    const int wid = tid >> 5;
    const int lane = tid & 31;
    const int group = lane >> 2;
    const int t4 = lane & 3;
    const int warpC = (wid & 1) * 32;
    const int warpR = (wid >> 1) * 16;

    const float* xb = x + (size_t)b * L_ * C_ + c0;

    float acc[2][2][4];
#pragma unroll
    for (int mt = 0; mt < 2; mt++)
#pragma unroll
        for (int nt = 0; nt < 2; nt++)
#pragma unroll
            for (int i = 0; i < 4; i++) acc[mt][nt][i] = 0.f;

#define ISSUE_CHUNK(l0, st)                                                        \
    {                                                                              \
        float* as_ = smh + (st)*4608;                                              \
        float* bs_ = smh + 9216 + (st)*4608;                                       \
        _Pragma("unroll") for (int i = 0; i < 4; i++) {                            \
            int task = tid + i * 256;                                              \
            int k = task >> 4, c4 = (task & 15) * 4;                               \
            uint32_t dst = (uint32_t)__cvta_generic_to_shared(&as_[k * 72 + c4]);  \
            const float* src = &xb[(size_t)((l0) + k) * C_ + c4];                  \
            asm volatile("cp.async.cg.shared.global [%0], [%1], 16;" ::"r"(dst),   \
                         "l"(src));                                                \
        }                                                                          \
        _Pragma("unroll") for (int i = 0; i < 4; i++) {                            \
            int task = tid + i * 256;                                              \
            int r = task >> 4, k4 = (task & 15) * 4;                               \
            uint32_t dst = (uint32_t)__cvta_generic_to_shared(&bs_[r * 72 + k4]);  \
            const float* src = &Wd[r * L_ + (l0) + k4];                            \
            asm volatile("cp.async.cg.shared.global [%0], [%1], 16;" ::"r"(dst),   \
                         "l"(src));                                                \
        }                                                                          \
        asm volatile("cp.async.commit_group;");                                    \
    }

    ISSUE_CHUNK(0, 0);

    for (int ch = 0; ch < 32; ch++) {
        if (ch < 31) {
            ISSUE_CHUNK((ch + 1) * 64, (ch + 1) & 1);
            asm volatile("cp.async.wait_group 1;");
        } else {
            asm volatile("cp.async.wait_group 0;");
        }
        __syncthreads();

        const float* as_ = smh + (ch & 1) * 4608;
        const float* bs_ = smh + 9216 + (ch & 1) * 4608;

#pragma unroll
        for (int ks = 0; ks < 8; ks++) {
            int k0 = ks * 8 + t4;
            uint32_t a[2][4];
#pragma unroll
            for (int mt = 0; mt < 2; mt++) {
                int cm = warpC + mt * 16 + group;
                a[mt][0] = __float_as_uint(as_[k0 * 72 + cm]);
                a[mt][1] = __float_as_uint(as_[k0 * 72 + cm + 8]);
                a[mt][2] = __float_as_uint(as_[(k0 + 4) * 72 + cm]);
                a[mt][3] = __float_as_uint(as_[(k0 + 4) * 72 + cm + 8]);
            }
#pragma unroll
            for (int nt = 0; nt < 2; nt++) {
                int rn = warpR + nt * 8 + group;
                uint32_t b0 = __float_as_uint(bs_[rn * 72 + k0]);
                uint32_t b1 = __float_as_uint(bs_[rn * 72 + k0 + 4]);
#pragma unroll
                for (int mt = 0; mt < 2; mt++)
                    mma_tf32(acc[mt][nt], a[mt][0], a[mt][1], a[mt][2], a[mt][3], b0, b1);
            }
        }
        __syncthreads();
    }
#undef ISSUE_CHUNK

    // epilogue
#pragma unroll
    for (int nt = 0; nt < 2; nt++) {
        int r = warpR + nt * 8 + t4 * 2;
        float b0v = bd[r], b1v = bd[r + 1];
#pragma unroll
        for (int mt = 0; mt < 2; mt++) {
            int c = c0 + warpC + mt * 16 + group;
            float2 v0 = {acc[mt][nt][0] + b0v, acc[mt][nt][1] + b1v};
            float2 v1 = {acc[mt][nt][2] + b0v, acc[mt][nt][3] + b1v};
            *(float2*)&g_hlow[((size_t)b * C_ + c) * R_ + r] = v0;
            *(float2*)&g_hlow[((size_t)b * C_ + c + 8) * R_ + r] = v1;
        }
    }
}

// ---------------------------------------------------------------------------
// Kernel 2a: partial kv sums. Grid (8, B), 256 thr; chunk = 64 tokens.
// ---------------------------------------------------------------------------
__global__ __launch_bounds__(256) void k_kv(const float* __restrict__ Wk,
                                            const float* __restrict__ Wv) {
    __shared__ float wA[64 * 65];
    __shared__ float wB[64 * 65];
    __shared__ float kv[64];

    const int b = blockIdx.y;
    const int chunk = blockIdx.x;
    const int tid = threadIdx.x;
    const int lane = tid & 31;
    const int w = tid >> 5;

    if (tid < 64) kv[tid] = 0.f;
#pragma unroll
    for (int i = 0; i < 16; i++) {
        int idx = tid + i * 256;
        int o = idx >> 6, s = idx & 63;
        wA[s * 65 + o] = Wk[idx];
        wB[s * 65 + o] = Wv[idx];
    }
    __syncthreads();

    float acc0 = 0.f, acc1 = 0.f;
#pragma unroll
    for (int it = 0; it < 8; it++) {
        int c = chunk * 64 + it * 8 + w;
        const float* hb = &g_hlow[((size_t)b * C_ + c) * R_];
        float h0 = hb[lane], h1 = hb[lane + 32];
        float k0 = 0.f, k1 = 0.f, v0 = 0.f, v1 = 0.f;
#pragma unroll
        for (int s = 0; s < 32; s++) {
            float ha = __shfl_sync(0xffffffffu, h0, s);
            float hc = __shfl_sync(0xffffffffu, h1, s);
            k0 += ha * wA[s * 65 + lane] + hc * wA[(s + 32) * 65 + lane];
            k1 += ha * wA[s * 65 + lane + 32] + hc * wA[(s + 32) * 65 + lane + 32];
            v0 += ha * wB[s * 65 + lane] + hc * wB[(s + 32) * 65 + lane];
            v1 += ha * wB[s * 65 + lane + 32] + hc * wB[(s + 32) * 65 + lane + 32];
        }
        float nk = k0 * k0 + k1 * k1;
#pragma unroll
        for (int off = 16; off > 0; off >>= 1) nk += __shfl_xor_sync(0xffffffffu, nk, off);
        float inv = 1.f / fmaxf(sqrtf(nk), 1e-12f);
        acc0 += k0 * inv * v0;
        acc1 += k1 * inv * v1;
    }
    atomicAdd(&kv[lane], acc0);
    atomicAdd(&kv[lane + 32], acc1);
    __syncthreads();
    if (tid < 64) g_kvpart[((size_t)b * 8 + chunk) * 64 + tid] = kv[tid];
}

// ---------------------------------------------------------------------------
// Kernel 2b: Q, gate, h_attn (bf16 out). Grid (8, B), 256 thr.
// ---------------------------------------------------------------------------
__global__ __launch_bounds__(256) void k_qg(const float* __restrict__ Wq,
                                            const float* __restrict__ Wg,
                                            const float* __restrict__ bg) {
    __shared__ float wA[64 * 65];
    __shared__ float wB[64 * 65];
    __shared__ float kv[64];

    const int b = blockIdx.y;
    const int chunk = blockIdx.x;
    const int tid = threadIdx.x;
    const int lane = tid & 31;
    const int w = tid >> 5;

    if (tid < 64) {
        float s = 0.f;
#pragma unroll
        for (int j = 0; j < 8; j++) s += g_kvpart[((size_t)b * 8 + j) * 64 + tid];
        kv[tid] = s;
    }
#pragma unroll
    for (int i = 0; i < 16; i++) {
        int idx = tid + i * 256;
        int o = idx >> 6, s = idx & 63;
        wA[s * 65 + o] = Wq[idx];
        wB[s * 65 + o] = Wg[idx];
    }
    __syncthreads();

    float kv0t = kv[lane], kv1t = kv[lane + 32];
    float bg0 = bg[lane], bg1 = bg[lane + 32];

#pragma unroll
    for (int it = 0; it < 8; it++) {
        int c = chunk * 64 + it * 8 + w;
        const float* hb = &g_hlow[((size_t)b * C_ + c) * R_];
        float h0 = hb[lane], h1 = hb[lane + 32];
        float q0 = 0.f, q1 = 0.f, g0 = 0.f, g1 = 0.f;
#pragma unroll
        for (int s = 0; s < 32; s++) {
            float ha = __shfl_sync(0xffffffffu, h0, s);
            float hc = __shfl_sync(0xffffffffu, h1, s);
            q0 += ha * wA[s * 65 + lane] + hc * wA[(s + 32) * 65 + lane];
            q1 += ha * wA[s * 65 + lane + 32] + hc * wA[(s + 32) * 65 + lane + 32];
            g0 += ha * wB[s * 65 + lane] + hc * wB[(s + 32) * 65 + lane];
            g1 += ha * wB[s * 65 + lane + 32] + hc * wB[(s + 32) * 65 + lane + 32];
        }
        float nq = q0 * q0 + q1 * q1;
#pragma unroll
        for (int off = 16; off > 0; off >>= 1) nq += __shfl_xor_sync(0xffffffffu, nq, off);
        float inv = 1.f / fmaxf(sqrtf(nq), 1e-12f);
        float ga0 = 1.f / (1.f + expf(-(g0 + bg0)));
        float ga1 = 1.f / (1.f + expf(-(g1 + bg1)));
        __nv_bfloat16* ob = &g_hattn[((size_t)b * C_ + c) * R_];
        ob[lane]      = __float2bfloat16(q0 * inv * kv0t * ga0);
        ob[lane + 32] = __float2bfloat16(q1 * inv * kv1t * ga1);
    }
}

// ---------------------------------------------------------------------------
// Kernel 3 (bf16 mma m16n8k16): mixed[l,c] = sum_r Wu[l,r]*h_attn[c,r];
// out = LN_c(x + alpha*(mixed + bu)). Grid (64, B), 512 thr.
// CTA tile: 32 l (m) x 512 c (n), full k=64 staged once.
// 16 warps: warp = (l-half lh=wid>>3) x (64-c span cw=wid&7).
// ---------------------------------------------------------------------------
__global__ __launch_bounds__(512, 2) void k_out(const float* __restrict__ x,
                                                const float* __restrict__ Wu,
                                                const float* __restrict__ bu,
                                                const float* __restrict__ gamma,
                                                const float* __restrict__ beta,
                                                const float* __restrict__ alpha_p,
                                                float* __restrict__ out) {
    extern __shared__ uint32_t sm3[];
    uint32_t* as_ = sm3;                 // [32][36] bf16x2 pairs of Wu
    uint32_t* bs_ = sm3 + 32 * 36;       // [512][36] bf16x2 pairs of h_attn
    float* outs = (float*)(sm3 + 32 * 36);  // alias over bs after mma: [32][516]

    const int b = blockIdx.y;
    const int l0 = blockIdx.x * 32;
    const int tid = threadIdx.x;
    const int wid = tid >> 5;
    const int lane = tid & 31;
    const int group = lane >> 2;
    const int t4 = lane & 3;
    const int lh = wid >> 3;
    const int cw = wid & 7;

    // fill A: Wu[l0+l][2p..2p+1] -> as[l][p]
#pragma unroll
    for (int i = 0; i < 2; i++) {
        int idx = tid + i * 512;
        int l = idx >> 5, p = idx & 31;
        float2 w = *(const float2*)&Wu[(size_t)(l0 + l) * R_ + 2 * p];
        __nv_bfloat162 h2 = __float22bfloat162_rn(w);
        as_[l * 36 + p] = *(uint32_t*)&h2;
    }
    // fill B: h_attn row c (64 bf16 = 8 uint4) -> bs[c][0..31]
    {
        const uint4* hb = (const uint4*)&g_hattn[(size_t)b * C_ * R_];
        int q = tid & 7;
#pragma unroll
        for (int i = 0; i < 8; i++) {
            int c = (tid >> 3) + i * 64;
            uint4 v = hb[c * 8 + q];
            bs_[c * 36 + 4 * q + 0] = v.x;
            bs_[c * 36 + 4 * q + 1] = v.y;
            bs_[c * 36 + 4 * q + 2] = v.z;
            bs_[c * 36 + 4 * q + 3] = v.w;
        }
    }
    __syncthreads();

    float acc[8][4];
#pragma unroll
    for (int nt = 0; nt < 8; nt++)
#pragma unroll
        for (int i = 0; i < 4; i++) acc[nt][i] = 0.f;

    const int rowA = lh * 16 + group;
#pragma unroll
    for (int ks = 0; ks < 4; ks++) {
        int pb = ks * 8 + t4;
        uint32_t a0 = as_[rowA * 36 + pb];
        uint32_t a1 = as_[(rowA + 8) * 36 + pb];
        uint32_t a2 = as_[rowA * 36 + pb + 4];
        uint32_t a3 = as_[(rowA + 8) * 36 + pb + 4];
#pragma unroll
        for (int nt = 0; nt < 8; nt++) {
            int cn = cw * 64 + nt * 8 + group;
            uint32_t b0 = bs_[cn * 36 + pb];
            uint32_t b1 = bs_[cn * 36 + pb + 4];
            mma_bf16(acc[nt], a0, a1, a2, a3, b0, b1);
        }
    }
    __syncthreads();  // all bs reads done; alias outs over bs

    // epilogue: mixed -> outs
#pragma unroll
    for (int nt = 0; nt < 8; nt++) {
        int c = cw * 64 + nt * 8 + t4 * 2;
        float2 v0 = {acc[nt][0], acc[nt][1]};
        float2 v1 = {acc[nt][2], acc[nt][3]};
        *(float2*)&outs[rowA * 516 + c] = v0;
        *(float2*)&outs[(rowA + 8) * 516 + c] = v1;
    }
    __syncthreads();

    // residual + LN over c; warp handles 2 rows
    const float alpha = *alpha_p;
#pragma unroll
    for (int rr = 0; rr < 2; rr++) {
        int li = wid * 2 + rr;
        float bul = bu[l0 + li];
        size_t xbase = ((size_t)b * L_ + l0 + li) * C_;
        float s = 0.f, ss = 0.f;
#pragma unroll
        for (int k = 0; k < 16; k++) {
            int c = lane + 32 * k;
            float m = outs[li * 516 + c];
            float v = x[xbase + c] + alpha * (m + bul);
            outs[li * 516 + c] = v;
            s += v;
            ss += v * v;
        }
#pragma unroll
        for (int off = 16; off > 0; off >>= 1) {
            s += __shfl_xor_sync(0xffffffffu, s, off);
            ss += __shfl_xor_sync(0xffffffffu, ss, off);
        }
        float mu = s * (1.f / 512.f);
        float var = ss * (1.f / 512.f) - mu * mu;
        float rstd = rsqrtf(var + 1e-5f);
#pragma unroll
        for (int k = 0; k < 16; k++) {
            int c = lane + 32 * k;
            float v = outs[li * 516 + c];
            out[xbase + c] = (v - mu) * rstd * gamma[c] + beta[c];
        }
    }
}

// ---------------------------------------------------------------------------
extern "C" void kernel_launch(void* const* d_in, const int* in_sizes, int n_in,
                              void* d_out, int out_size) {
    const float* x     = (const float*)d_in[0];
    const float* Wd    = (const float*)d_in[1];
    const float* bd    = (const float*)d_in[2];
    const float* Wq    = (const float*)d_in[3];
    const float* Wk    = (const float*)d_in[4];
    const float* Wv    = (const float*)d_in[5];
    const float* Wg    = (const float*)d_in[6];
    const float* bg    = (const float*)d_in[7];
    const float* Wu    = (const float*)d_in[8];
    const float* bu    = (const float*)d_in[9];
    const float* gamma = (const float*)d_in[10];
    const float* beta  = (const float*)d_in[11];
    const float* alpha = (const float*)d_in[12];
    float* out = (float*)d_out;

    static const int smem1 = 4 * 64 * 72 * 4;                 // 73728 B
    static const int smem3 = (32 * 36 + 512 * 36) * 4;        // 78336 B
    static bool attr_set = false;
    if (!attr_set) {
        cudaFuncSetAttribute(k_hlow, cudaFuncAttributeMaxDynamicSharedMemorySize, smem1);
        cudaFuncSetAttribute(k_out, cudaFuncAttributeMaxDynamicSharedMemorySize, smem3);
        attr_set = true;
    }

    k_hlow<<<dim3(8, B_), 256, smem1>>>(x, Wd, bd);
    k_kv<<<dim3(8, B_), 256>>>(Wk, Wv);
    k_qg<<<dim3(8, B_), 256>>>(Wq, Wg, bg);
    k_out<<<dim3(64, B_), 512, smem3>>>(x, Wu, bu, gamma, beta, alpha, out);
}